// round 16
// baseline (speedup 1.0000x reference)
#include <cuda_runtime.h>
#include <cuda_fp16.h>

typedef unsigned long long U64;

// ---------------- packed f32x2 helpers (Blackwell FFMA2, PTX-only) ----------------
__device__ __forceinline__ U64 pk2(float x, float y) {
    U64 r; asm("mov.b64 %0, {%1, %2};" : "=l"(r) : "f"(x), "f"(y)); return r;
}
__device__ __forceinline__ float lo2(U64 v) {
    float x; asm("{ .reg .f32 hi; mov.b64 {%0, hi}, %1; }" : "=f"(x) : "l"(v)); return x;
}
__device__ __forceinline__ float hi2(U64 v) {
    float y; asm("{ .reg .f32 lo; mov.b64 {lo, %0}, %1; }" : "=f"(y) : "l"(v)); return y;
}
__device__ __forceinline__ U64 fma2(U64 a, U64 b, U64 c) {
    U64 d; asm("fma.rn.f32x2 %0, %1, %2, %3;" : "=l"(d) : "l"(a), "l"(b), "l"(c)); return d;
}
__device__ __forceinline__ U64 add2(U64 a, U64 b) {
    U64 d; asm("add.rn.f32x2 %0, %1, %2;" : "=l"(d) : "l"(a), "l"(b)); return d;
}

// ---------------- fast transcendentals ----------------
__device__ __forceinline__ float rsqf(float x) { float r; asm("rsqrt.approx.f32 %0, %1;" : "=f"(r) : "f"(x)); return r; }
__device__ __forceinline__ float tanh_ap(float x) { float r; asm("tanh.approx.f32 %0, %1;" : "=f"(r) : "f"(x)); return r; }
__device__ __forceinline__ float sigm_ap(float v) {
    return fmaf(tanh_ap(0.5f * v), 0.5f, 0.5f);
}

static constexpr int Tn = 1000;
static constexpr int In = 13;
static constexpr int Hn = 13;
static constexpr int Bn = 2048;
static constexpr long long OUT_ELEMS = (long long)Bn * Tn * 2 * Hn;  // 53,248,000
static constexpr long long HN_ELEMS  = 2LL * Bn * Hn;

// Scratch: gate preactivations (i,f,g,o) as half4 (uint2) per (t,k),
// dir-major [d][b][t][k].  426 MB.
__device__ uint2 g2h[2LL * Bn * Tn * Hn];

// =====================================================================
// Kernel A (exact R10 body, proven ~187us): one THREAD per (b, 2 t's).
// LayerNorm folded into weights: y = rs*(W'.x - mu*u) + v; each weight
// LDS.64 feeds two fma2; staged in smem; linear coalesced copy-out.
// launch_bounds(128,2): enough regs for 52 live U64 accumulators.
// =====================================================================
__global__ void __launch_bounds__(128, 2) xpre_kernel(
    const float* __restrict__ x,
    const float* __restrict__ ln_w, const float* __restrict__ ln_b,
    const float* __restrict__ wih_f, const float* __restrict__ bih_f, const float* __restrict__ bhh_f,
    const float* __restrict__ wih_b, const float* __restrict__ bih_b, const float* __restrict__ bhh_b)
{
    __shared__ __align__(8) uint2 ssm[256 * 13];
    __shared__ __align__(8) float wsm[13][52][2];
    __shared__ __align__(8) float usm[52][2];
    __shared__ __align__(8) float vsm[52][2];

    const int tid = threadIdx.x;

    if (tid < 104) {
        const int half    = tid & 1;
        const int pairIdx = tid >> 1;
        const int d       = pairIdx / 26;
        const int p       = pairIdx % 26;
        const int grp     = p / 13;
        const int k13     = p % 13;
        const int row     = grp * 26 + k13 + half * 13;
        const float* Wm = d ? wih_b : wih_f;
        const float* Bi = d ? bih_b : bih_f;
        const float* Bh = d ? bhh_b : bhh_f;
        float u = 0.0f;
        float v = __ldg(&Bi[row]) + __ldg(&Bh[row]);
#pragma unroll
        for (int j = 0; j < In; ++j) {
            const float wv = __ldg(&Wm[row * In + j]);
            const float wp = wv * __ldg(&ln_w[j]);
            wsm[j][pairIdx][half] = wp;
            u += wp;
            v = fmaf(wv, __ldg(&ln_b[j]), v);
        }
        usm[pairIdx][half] = u;
        vsm[pairIdx][half] = v;
    }
    __syncthreads();

    const int b  = blockIdx.y;
    const int t0 = blockIdx.x * 256;
    const int tA = t0 + tid;
    const int tB = tA + 128;
    const bool actA = (tA < Tn);
    const bool actB = (tB < Tn);
    const int nvalid = (Tn - t0 < 256) ? (Tn - t0) : 256;

    float xa[In], xb[In];
    float SA = 0.0f, S2A = 0.0f, SB = 0.0f, S2B = 0.0f;
    const float* xpA = x + ((long long)b * Tn + tA) * In;
    const float* xpB = x + ((long long)b * Tn + tB) * In;
#pragma unroll
    for (int j = 0; j < In; ++j) {
        xa[j] = actA ? __ldg(xpA + j) : 0.0f;
        xb[j] = actB ? __ldg(xpB + j) : 0.0f;
        SA += xa[j];  S2A = fmaf(xa[j], xa[j], S2A);
        SB += xb[j];  S2B = fmaf(xb[j], xb[j], S2B);
    }
    const float muA = SA * (1.0f / 13.0f);
    const float rsA = rsqf(fmaf(-muA, muA, S2A * (1.0f / 13.0f)) + 1e-5f);
    const float muB = SB * (1.0f / 13.0f);
    const float rsB = rsqf(fmaf(-muB, muB, S2B * (1.0f / 13.0f)) + 1e-5f);
    const U64 nmuA2 = pk2(-muA, -muA), rsA2 = pk2(rsA, rsA);
    const U64 nmuB2 = pk2(-muB, -muB), rsB2 = pk2(rsB, rsB);

#pragma unroll
    for (int d = 0; d < 2; ++d) {
        U64 accA[26], accB[26];
#pragma unroll
        for (int p = 0; p < 26; ++p) { accA[p] = 0ULL; accB[p] = 0ULL; }

        for (int j = 0; j < In; ++j) {
            const U64 xa2 = pk2(xa[j], xa[j]);
            const U64 xb2 = pk2(xb[j], xb[j]);
#pragma unroll
            for (int p = 0; p < 26; ++p) {
                const U64 wv = *(const U64*)&wsm[j][d * 26 + p][0];
                accA[p] = fma2(wv, xa2, accA[p]);
                accB[p] = fma2(wv, xb2, accB[p]);
            }
        }

#pragma unroll
        for (int p = 0; p < 13; ++p) {
            const U64 uIF = *(const U64*)&usm[d * 26 + p][0];
            const U64 vIF = *(const U64*)&vsm[d * 26 + p][0];
            const U64 uGO = *(const U64*)&usm[d * 26 + 13 + p][0];
            const U64 vGO = *(const U64*)&vsm[d * 26 + 13 + p][0];

            const U64 yAif = fma2(fma2(uIF, nmuA2, accA[p]),      rsA2, vIF);
            const U64 yAgo = fma2(fma2(uGO, nmuA2, accA[13 + p]), rsA2, vGO);
            const U64 yBif = fma2(fma2(uIF, nmuB2, accB[p]),      rsB2, vIF);
            const U64 yBgo = fma2(fma2(uGO, nmuB2, accB[13 + p]), rsB2, vGO);

            const __half2 hAif = __float22half2_rn(make_float2(lo2(yAif), hi2(yAif)));
            const __half2 hAgo = __float22half2_rn(make_float2(lo2(yAgo), hi2(yAgo)));
            const __half2 hBif = __float22half2_rn(make_float2(lo2(yBif), hi2(yBif)));
            const __half2 hBgo = __float22half2_rn(make_float2(lo2(yBgo), hi2(yBgo)));

            uint2 uA, uB;
            uA.x = *(const unsigned*)&hAif;  uA.y = *(const unsigned*)&hAgo;
            uB.x = *(const unsigned*)&hBif;  uB.y = *(const unsigned*)&hBgo;
            ssm[tid * 13 + p]         = uA;
            ssm[(tid + 128) * 13 + p] = uB;
        }
        __syncthreads();

        uint2* dst = g2h + (((long long)d * Bn + b) * Tn + t0) * Hn;
        const int n = nvalid * 13;
        for (int i = tid; i < n; i += 128)
            dst[i] = ssm[i];
        __syncthreads();
    }
}

// =====================================================================
// Kernel B: recurrence (R8 body, prefetch deepened 4 -> 8). One warp
// per batch row; lanes 0-15 fwd, 16-31 bwd. 8-deep guarded LDG.64
// prefetch: 8 outstanding g-loads per warp halve the effective
// per-step DRAM-latency term (lat/8 vs lat/4). h DUPLICATED (h,h) in
// smem; dual accumulators; tanh.approx activations.
// =====================================================================
__global__ void __launch_bounds__(64, 7) rec_kernel(
    const float* __restrict__ whh_f, const float* __restrict__ whh_b,
    float* __restrict__ out)
{
    __shared__ __align__(8) float2 hsm[2][2][2][14];  // [warp][buf][dir][pad 14]

    const int lane = threadIdx.x & 31;
    const int w    = threadIdx.x >> 5;
    const int dir  = lane >> 4;
    const int k    = lane & 15;
    const bool active = (k < Hn);
    const int kk   = active ? k : 0;
    const int b    = blockIdx.x * 2 + w;

    const float* Whh = dir ? whh_b : whh_f;

    U64 wif[In], wgo[In];
#pragma unroll
    for (int j = 0; j < In; ++j) {
        wif[j] = pk2(__ldg(&Whh[kk * Hn + j]),            __ldg(&Whh[(Hn + kk) * Hn + j]));
        wgo[j] = pk2(__ldg(&Whh[(2 * Hn + kk) * Hn + j]), __ldg(&Whh[(3 * Hn + kk) * Hn + j]));
    }

    if (active) {
        hsm[w][0][dir][k] = make_float2(0.0f, 0.0f);
        hsm[w][1][dir][k] = make_float2(0.0f, 0.0f);
    }
    __syncwarp();

    // g2h layout [d][b][t][k]
    const uint2* gp = g2h + (((long long)dir * Bn + b) * Tn + (dir ? Tn - 1 : 0)) * Hn + kk;
    const int dgp = dir ? -Hn : Hn;

    float* op = out + (long long)b * (Tn * 2 * Hn)
                    + (dir ? (long long)(Tn - 1) * 2 * Hn : 0) + dir * Hn + kk;
    const int dop = dir ? -(2 * Hn) : (2 * Hn);

    float c = 0.0f, h = 0.0f;

    uint2 gb[8];
#pragma unroll
    for (int i = 0; i < 8; ++i) { gb[i] = __ldg(gp); gp += dgp; }

#pragma unroll 4
    for (int t = 0; t < Tn; ++t) {
        const uint2 graw = gb[t & 7];
        if (t + 8 < Tn) { gb[t & 7] = __ldg(gp); gp += dgp; }

        // fp16 -> fp32 (independent, hidden by pipeline)
        const float2 gxy = __half22float2(*(const __half2*)&graw.x);
        const float2 gzw = __half22float2(*(const __half2*)&graw.y);

        const int cur = t & 1, nxt = cur ^ 1;

        U64 aif0 = pk2(gxy.x, gxy.y), aif1 = 0ULL;
        U64 ago0 = pk2(gzw.x, gzw.y), ago1 = 0ULL;
#pragma unroll
        for (int j = 0; j < 12; j += 2) {
            const U64 h0 = *(const U64*)&hsm[w][cur][dir][j];
            const U64 h1 = *(const U64*)&hsm[w][cur][dir][j + 1];
            aif0 = fma2(wif[j],     h0, aif0);
            ago0 = fma2(wgo[j],     h0, ago0);
            aif1 = fma2(wif[j + 1], h1, aif1);
            ago1 = fma2(wgo[j + 1], h1, ago1);
        }
        {
            const U64 h12 = *(const U64*)&hsm[w][cur][dir][12];
            aif0 = fma2(wif[12], h12, aif0);
            ago0 = fma2(wgo[12], h12, ago0);
        }
        const U64 aif = add2(aif0, aif1);
        const U64 ago = add2(ago0, ago1);

        const float gi = sigm_ap(lo2(aif));
        const float gf = sigm_ap(hi2(aif));
        const float gg = tanh_ap(lo2(ago));
        const float go = sigm_ap(hi2(ago));

        c = fmaf(gf, c, gi * gg);
        h = go * tanh_ap(c);

        if (active) { hsm[w][nxt][dir][k] = make_float2(h, h); *op = h; }
        op += dop;
        __syncwarp();
    }

    if (active) {
        float* hn = out + OUT_ELEMS + (long long)dir * (Bn * Hn) + (long long)b * Hn + k;
        hn[0] = h;
        hn[HN_ELEMS] = c;
    }
}

extern "C" void kernel_launch(void* const* d_in, const int* in_sizes, int n_in,
                              void* d_out, int out_size)
{
    const float* x     = (const float*)d_in[0];
    const float* ln_w  = (const float*)d_in[1];
    const float* ln_b  = (const float*)d_in[2];
    const float* wih_f = (const float*)d_in[3];
    const float* whh_f = (const float*)d_in[4];
    const float* bih_f = (const float*)d_in[5];
    const float* bhh_f = (const float*)d_in[6];
    const float* wih_b = (const float*)d_in[7];
    const float* whh_b = (const float*)d_in[8];
    const float* bih_b = (const float*)d_in[9];
    const float* bhh_b = (const float*)d_in[10];
    float* out = (float*)d_out;

    // Kernel A: 2 timesteps per thread; grid (4, 2048)
    dim3 gridA((Tn + 255) / 256, Bn);
    xpre_kernel<<<gridA, 128>>>(x, ln_w, ln_b,
                                wih_f, bih_f, bhh_f,
                                wih_b, bih_b, bhh_b);

    // Kernel B: one warp per batch row, 2 warps/block
    rec_kernel<<<Bn / 2, 64>>>(whh_f, whh_b, out);
}

// round 17
// speedup vs baseline: 1.6684x; 1.6684x over previous
#include <cuda_runtime.h>
#include <cuda_fp16.h>

typedef unsigned long long U64;

// ---------------- packed f32x2 helpers (Blackwell FFMA2, PTX-only) ----------------
__device__ __forceinline__ U64 pk2(float x, float y) {
    U64 r; asm("mov.b64 %0, {%1, %2};" : "=l"(r) : "f"(x), "f"(y)); return r;
}
__device__ __forceinline__ float lo2(U64 v) {
    float x; asm("{ .reg .f32 hi; mov.b64 {%0, hi}, %1; }" : "=f"(x) : "l"(v)); return x;
}
__device__ __forceinline__ float hi2(U64 v) {
    float y; asm("{ .reg .f32 lo; mov.b64 {lo, %0}, %1; }" : "=f"(y) : "l"(v)); return y;
}
__device__ __forceinline__ U64 fma2(U64 a, U64 b, U64 c) {
    U64 d; asm("fma.rn.f32x2 %0, %1, %2, %3;" : "=l"(d) : "l"(a), "l"(b), "l"(c)); return d;
}
__device__ __forceinline__ U64 add2(U64 a, U64 b) {
    U64 d; asm("add.rn.f32x2 %0, %1, %2;" : "=l"(d) : "l"(a), "l"(b)); return d;
}

// ---------------- fast transcendentals ----------------
__device__ __forceinline__ float rsqf(float x) { float r; asm("rsqrt.approx.f32 %0, %1;" : "=f"(r) : "f"(x)); return r; }
__device__ __forceinline__ float tanh_ap(float x) { float r; asm("tanh.approx.f32 %0, %1;" : "=f"(r) : "f"(x)); return r; }
__device__ __forceinline__ float sigm_ap(float v) {
    return fmaf(tanh_ap(0.5f * v), 0.5f, 0.5f);
}

static constexpr int Tn = 1000;
static constexpr int In = 13;
static constexpr int Hn = 13;
static constexpr int Bn = 2048;
static constexpr long long OUT_ELEMS = (long long)Bn * Tn * 2 * Hn;  // 53,248,000
static constexpr long long HN_ELEMS  = 2LL * Bn * Hn;

// Scratch: gate preactivations (i,f,g,o) as half4 (uint2) per (t,k),
// dir-major [d][b][t][k].  426 MB.
__device__ uint2 g2h[2LL * Bn * Tn * Hn];

// =====================================================================
// Kernel A (exact R10 body, proven ~187us): one THREAD per (b, 2 t's).
// LayerNorm folded into weights: y = rs*(W'.x - mu*u) + v; each weight
// LDS.64 feeds two fma2; staged in smem; linear coalesced copy-out.
// =====================================================================
__global__ void __launch_bounds__(128, 2) xpre_kernel(
    const float* __restrict__ x,
    const float* __restrict__ ln_w, const float* __restrict__ ln_b,
    const float* __restrict__ wih_f, const float* __restrict__ bih_f, const float* __restrict__ bhh_f,
    const float* __restrict__ wih_b, const float* __restrict__ bih_b, const float* __restrict__ bhh_b)
{
    __shared__ __align__(8) uint2 ssm[256 * 13];
    __shared__ __align__(8) float wsm[13][52][2];
    __shared__ __align__(8) float usm[52][2];
    __shared__ __align__(8) float vsm[52][2];

    const int tid = threadIdx.x;

    if (tid < 104) {
        const int half    = tid & 1;
        const int pairIdx = tid >> 1;
        const int d       = pairIdx / 26;
        const int p       = pairIdx % 26;
        const int grp     = p / 13;
        const int k13     = p % 13;
        const int row     = grp * 26 + k13 + half * 13;
        const float* Wm = d ? wih_b : wih_f;
        const float* Bi = d ? bih_b : bih_f;
        const float* Bh = d ? bhh_b : bhh_f;
        float u = 0.0f;
        float v = __ldg(&Bi[row]) + __ldg(&Bh[row]);
#pragma unroll
        for (int j = 0; j < In; ++j) {
            const float wv = __ldg(&Wm[row * In + j]);
            const float wp = wv * __ldg(&ln_w[j]);
            wsm[j][pairIdx][half] = wp;
            u += wp;
            v = fmaf(wv, __ldg(&ln_b[j]), v);
        }
        usm[pairIdx][half] = u;
        vsm[pairIdx][half] = v;
    }
    __syncthreads();

    const int b  = blockIdx.y;
    const int t0 = blockIdx.x * 256;
    const int tA = t0 + tid;
    const int tB = tA + 128;
    const bool actA = (tA < Tn);
    const bool actB = (tB < Tn);
    const int nvalid = (Tn - t0 < 256) ? (Tn - t0) : 256;

    float xa[In], xb[In];
    float SA = 0.0f, S2A = 0.0f, SB = 0.0f, S2B = 0.0f;
    const float* xpA = x + ((long long)b * Tn + tA) * In;
    const float* xpB = x + ((long long)b * Tn + tB) * In;
#pragma unroll
    for (int j = 0; j < In; ++j) {
        xa[j] = actA ? __ldg(xpA + j) : 0.0f;
        xb[j] = actB ? __ldg(xpB + j) : 0.0f;
        SA += xa[j];  S2A = fmaf(xa[j], xa[j], S2A);
        SB += xb[j];  S2B = fmaf(xb[j], xb[j], S2B);
    }
    const float muA = SA * (1.0f / 13.0f);
    const float rsA = rsqf(fmaf(-muA, muA, S2A * (1.0f / 13.0f)) + 1e-5f);
    const float muB = SB * (1.0f / 13.0f);
    const float rsB = rsqf(fmaf(-muB, muB, S2B * (1.0f / 13.0f)) + 1e-5f);
    const U64 nmuA2 = pk2(-muA, -muA), rsA2 = pk2(rsA, rsA);
    const U64 nmuB2 = pk2(-muB, -muB), rsB2 = pk2(rsB, rsB);

#pragma unroll
    for (int d = 0; d < 2; ++d) {
        U64 accA[26], accB[26];
#pragma unroll
        for (int p = 0; p < 26; ++p) { accA[p] = 0ULL; accB[p] = 0ULL; }

        for (int j = 0; j < In; ++j) {
            const U64 xa2 = pk2(xa[j], xa[j]);
            const U64 xb2 = pk2(xb[j], xb[j]);
#pragma unroll
            for (int p = 0; p < 26; ++p) {
                const U64 wv = *(const U64*)&wsm[j][d * 26 + p][0];
                accA[p] = fma2(wv, xa2, accA[p]);
                accB[p] = fma2(wv, xb2, accB[p]);
            }
        }

#pragma unroll
        for (int p = 0; p < 13; ++p) {
            const U64 uIF = *(const U64*)&usm[d * 26 + p][0];
            const U64 vIF = *(const U64*)&vsm[d * 26 + p][0];
            const U64 uGO = *(const U64*)&usm[d * 26 + 13 + p][0];
            const U64 vGO = *(const U64*)&vsm[d * 26 + 13 + p][0];

            const U64 yAif = fma2(fma2(uIF, nmuA2, accA[p]),      rsA2, vIF);
            const U64 yAgo = fma2(fma2(uGO, nmuA2, accA[13 + p]), rsA2, vGO);
            const U64 yBif = fma2(fma2(uIF, nmuB2, accB[p]),      rsB2, vIF);
            const U64 yBgo = fma2(fma2(uGO, nmuB2, accB[13 + p]), rsB2, vGO);

            const __half2 hAif = __float22half2_rn(make_float2(lo2(yAif), hi2(yAif)));
            const __half2 hAgo = __float22half2_rn(make_float2(lo2(yAgo), hi2(yAgo)));
            const __half2 hBif = __float22half2_rn(make_float2(lo2(yBif), hi2(yBif)));
            const __half2 hBgo = __float22half2_rn(make_float2(lo2(yBgo), hi2(yBgo)));

            uint2 uA, uB;
            uA.x = *(const unsigned*)&hAif;  uA.y = *(const unsigned*)&hAgo;
            uB.x = *(const unsigned*)&hBif;  uB.y = *(const unsigned*)&hBgo;
            ssm[tid * 13 + p]         = uA;
            ssm[(tid + 128) * 13 + p] = uB;
        }
        __syncthreads();

        uint2* dst = g2h + (((long long)d * Bn + b) * Tn + t0) * Hn;
        const int n = nvalid * 13;
        for (int i = tid; i < n; i += 128)
            dst[i] = ssm[i];
        __syncthreads();
    }
}

// =====================================================================
// Kernel B: recurrence (R8 body; prefetch ring 8 deep, loop unrolled 8
// so ring indices are compile-time constants -> ring stays in regs).
// One warp per batch row; lanes 0-15 fwd, 16-31 bwd. h DUPLICATED
// (h,h) in smem; dual accumulators; tanh.approx activations.
// =====================================================================
__global__ void __launch_bounds__(64, 7) rec_kernel(
    const float* __restrict__ whh_f, const float* __restrict__ whh_b,
    float* __restrict__ out)
{
    __shared__ __align__(8) float2 hsm[2][2][2][14];  // [warp][buf][dir][pad 14]

    const int lane = threadIdx.x & 31;
    const int w    = threadIdx.x >> 5;
    const int dir  = lane >> 4;
    const int k    = lane & 15;
    const bool active = (k < Hn);
    const int kk   = active ? k : 0;
    const int b    = blockIdx.x * 2 + w;

    const float* Whh = dir ? whh_b : whh_f;

    U64 wif[In], wgo[In];
#pragma unroll
    for (int j = 0; j < In; ++j) {
        wif[j] = pk2(__ldg(&Whh[kk * Hn + j]),            __ldg(&Whh[(Hn + kk) * Hn + j]));
        wgo[j] = pk2(__ldg(&Whh[(2 * Hn + kk) * Hn + j]), __ldg(&Whh[(3 * Hn + kk) * Hn + j]));
    }

    if (active) {
        hsm[w][0][dir][k] = make_float2(0.0f, 0.0f);
        hsm[w][1][dir][k] = make_float2(0.0f, 0.0f);
    }
    __syncwarp();

    // g2h layout [d][b][t][k]
    const uint2* gp = g2h + (((long long)dir * Bn + b) * Tn + (dir ? Tn - 1 : 0)) * Hn + kk;
    const int dgp = dir ? -Hn : Hn;

    float* op = out + (long long)b * (Tn * 2 * Hn)
                    + (dir ? (long long)(Tn - 1) * 2 * Hn : 0) + dir * Hn + kk;
    const int dop = dir ? -(2 * Hn) : (2 * Hn);

    float c = 0.0f, h = 0.0f;

    uint2 gb[8];
#pragma unroll
    for (int i = 0; i < 8; ++i) { gb[i] = __ldg(gp); gp += dgp; }

#pragma unroll 8
    for (int t = 0; t < Tn; ++t) {
        const uint2 graw = gb[t & 7];          // static after unroll-8
        if (t + 8 < Tn) { gb[t & 7] = __ldg(gp); gp += dgp; }

        // fp16 -> fp32 (independent, hidden by pipeline)
        const float2 gxy = __half22float2(*(const __half2*)&graw.x);
        const float2 gzw = __half22float2(*(const __half2*)&graw.y);

        const int cur = t & 1, nxt = cur ^ 1;

        U64 aif0 = pk2(gxy.x, gxy.y), aif1 = 0ULL;
        U64 ago0 = pk2(gzw.x, gzw.y), ago1 = 0ULL;
#pragma unroll
        for (int j = 0; j < 12; j += 2) {
            const U64 h0 = *(const U64*)&hsm[w][cur][dir][j];
            const U64 h1 = *(const U64*)&hsm[w][cur][dir][j + 1];
            aif0 = fma2(wif[j],     h0, aif0);
            ago0 = fma2(wgo[j],     h0, ago0);
            aif1 = fma2(wif[j + 1], h1, aif1);
            ago1 = fma2(wgo[j + 1], h1, ago1);
        }
        {
            const U64 h12 = *(const U64*)&hsm[w][cur][dir][12];
            aif0 = fma2(wif[12], h12, aif0);
            ago0 = fma2(wgo[12], h12, ago0);
        }
        const U64 aif = add2(aif0, aif1);
        const U64 ago = add2(ago0, ago1);

        const float gi = sigm_ap(lo2(aif));
        const float gf = sigm_ap(hi2(aif));
        const float gg = tanh_ap(lo2(ago));
        const float go = sigm_ap(hi2(ago));

        c = fmaf(gf, c, gi * gg);
        h = go * tanh_ap(c);

        if (active) { hsm[w][nxt][dir][k] = make_float2(h, h); *op = h; }
        op += dop;
        __syncwarp();
    }

    if (active) {
        float* hn = out + OUT_ELEMS + (long long)dir * (Bn * Hn) + (long long)b * Hn + k;
        hn[0] = h;
        hn[HN_ELEMS] = c;
    }
}

extern "C" void kernel_launch(void* const* d_in, const int* in_sizes, int n_in,
                              void* d_out, int out_size)
{
    const float* x     = (const float*)d_in[0];
    const float* ln_w  = (const float*)d_in[1];
    const float* ln_b  = (const float*)d_in[2];
    const float* wih_f = (const float*)d_in[3];
    const float* whh_f = (const float*)d_in[4];
    const float* bih_f = (const float*)d_in[5];
    const float* bhh_f = (const float*)d_in[6];
    const float* bih_b_dummy = nullptr; (void)bih_b_dummy;
    const float* wih_b = (const float*)d_in[7];
    const float* whh_b = (const float*)d_in[8];
    const float* bih_b = (const float*)d_in[9];
    const float* bhh_b = (const float*)d_in[10];
    float* out = (float*)d_out;

    // Kernel A: 2 timesteps per thread; grid (4, 2048)
    dim3 gridA((Tn + 255) / 256, Bn);
    xpre_kernel<<<gridA, 128>>>(x, ln_w, ln_b,
                                wih_f, bih_f, bhh_f,
                                wih_b, bih_b, bhh_b);

    // Kernel B: one warp per batch row, 2 warps/block
    rec_kernel<<<Bn / 2, 64>>>(whh_f, whh_b, out);
}